// round 15
// baseline (speedup 1.0000x reference)
#include <cuda_runtime.h>
#include <cuda_bf16.h>
#include <cstdint>
#include <math.h>

#define BB 8
#define SS 8192
#define HH 768
#define NH 12
#define HD 64
#define NBN 4
#define RR 48
#define SCALEF 0.125f
#define NSPLIT 16

// ---------------- global scratch ----------------
__device__ __nv_bfloat16 g_qwh[BB*RR*HH];
__device__ __nv_bfloat16 g_qwl[BB*RR*HH];
__device__ float g_sc[(size_t)BB*RR*SS];
__device__ __nv_bfloat16 g_ath[(size_t)BB*RR*SS];
__device__ __nv_bfloat16 g_atl[(size_t)BB*RR*SS];
__device__ float g_part[(size_t)BB*NSPLIT*RR*HH];
__device__ float g_o[BB*NBN*HH];

// ---------------- helpers ----------------
__device__ __forceinline__ uint32_t smem_u32(const void* p) {
    uint32_t a;
    asm("{ .reg .u64 t; cvta.to.shared.u64 t, %1; cvt.u32.u64 %0, t; }" : "=r"(a) : "l"(p));
    return a;
}
__device__ __forceinline__ void ldsm4(uint32_t* r, uint32_t a) {
    asm volatile("ldmatrix.sync.aligned.m8n8.x4.shared.b16 {%0,%1,%2,%3}, [%4];"
        : "=r"(r[0]), "=r"(r[1]), "=r"(r[2]), "=r"(r[3]) : "r"(a));
}
__device__ __forceinline__ void ldsm4t(uint32_t* r, uint32_t a) {
    asm volatile("ldmatrix.sync.aligned.m8n8.x4.trans.shared.b16 {%0,%1,%2,%3}, [%4];"
        : "=r"(r[0]), "=r"(r[1]), "=r"(r[2]), "=r"(r[3]) : "r"(a));
}
__device__ __forceinline__ void mma_bf16(float* c, const uint32_t* a, uint32_t b0, uint32_t b1) {
    asm volatile("mma.sync.aligned.m16n8k16.row.col.f32.bf16.bf16.f32 "
        "{%0,%1,%2,%3}, {%4,%5,%6,%7}, {%8,%9}, {%0,%1,%2,%3};"
        : "+f"(c[0]), "+f"(c[1]), "+f"(c[2]), "+f"(c[3])
        : "r"(a[0]), "r"(a[1]), "r"(a[2]), "r"(a[3]), "r"(b0), "r"(b1));
}
__device__ __forceinline__ uint32_t pk2(float a, float b) {
    __nv_bfloat162 t = __floats2bfloat162_rn(a, b);
    return *reinterpret_cast<uint32_t*>(&t);
}
__device__ __forceinline__ float rz(float v) {
    return v - __bfloat162float(__float2bfloat16_rn(v));
}

// ========== Kernel 1: qw projection, split over 3 c-chunks (288 CTAs) ==========
__global__ void __launch_bounds__(256) k_qw(const float* __restrict__ x,
                                            const float* __restrict__ wq,
                                            const float* __restrict__ wkv) {
    int cchunk = blockIdx.x;
    int b = blockIdx.y / NH, h = blockIdx.y % NH;
    __shared__ float sx[NBN][HH];
    __shared__ float sq[NBN][HD];
    for (int idx = threadIdx.x; idx < NBN * HH; idx += 256) {
        int t = idx / HH, c = idx % HH;
        sx[t][c] = x[((size_t)b * SS + t) * HH + c];
    }
    __syncthreads();
    {
        int d = threadIdx.x >> 2, s = threadIdx.x & 3;
        const float4* wr = reinterpret_cast<const float4*>(wq + (size_t)(h * HD + d) * HH);
        float a[NBN] = {0.f, 0.f, 0.f, 0.f};
        #pragma unroll 4
        for (int kk = 0; kk < 48; kk++) {
            int c4 = s + kk * 4;
            float4 wv = wr[c4];
            #pragma unroll
            for (int t = 0; t < NBN; t++) {
                float4 sv = reinterpret_cast<const float4*>(sx[t])[c4];
                a[t] += wv.x * sv.x + wv.y * sv.y + wv.z * sv.z + wv.w * sv.w;
            }
        }
        #pragma unroll
        for (int t = 0; t < NBN; t++) {
            a[t] += __shfl_xor_sync(0xffffffffu, a[t], 1);
            a[t] += __shfl_xor_sync(0xffffffffu, a[t], 2);
        }
        if (s == 0)
            #pragma unroll
            for (int t = 0; t < NBN; t++) sq[t][d] = a[t];
    }
    __syncthreads();
    {
        int c = cchunk * 256 + threadIdx.x;
        float a[NBN] = {0.f, 0.f, 0.f, 0.f};
        #pragma unroll 8
        for (int d = 0; d < HD; d++) {
            float wv = wkv[(size_t)(h * HD + d) * HH + c];
            #pragma unroll
            for (int t = 0; t < NBN; t++) a[t] += sq[t][d] * wv;
        }
        #pragma unroll
        for (int t = 0; t < NBN; t++) {
            float v = a[t] * SCALEF;
            size_t idx = (size_t)(b * RR + h * NBN + t) * HH + c;
            __nv_bfloat16 hi = __float2bfloat16_rn(v);
            g_qwh[idx] = hi;
            g_qwl[idx] = __float2bfloat16_rn(v - __bfloat162float(hi));
        }
    }
}

// =========== Kernel 2: scores, distance-2 X prefetch, double-buffered ===========
#define SXP 40
#define SC_TOT 56320
__global__ void __launch_bounds__(256) k_scores_mma(const float* __restrict__ x) {
    extern __shared__ __align__(16) char dsm[];
    const uint32_t ub = smem_u32(dsm);

    const int tid = threadIdx.x, w = tid >> 5, l = tid & 31;
    const int b = blockIdx.y;
    const int y0 = blockIdx.x * 128;

    const float* xb = x + ((size_t)b * SS + y0) * HH;
    const __nv_bfloat16* qh = g_qwh + (size_t)b * RR * HH;
    const __nv_bfloat16* ql = g_qwl + (size_t)b * RR * HH;

    float acc[6][4];
    #pragma unroll
    for (int n = 0; n < 6; n++)
        #pragma unroll
        for (int k = 0; k < 4; k++) acc[n][k] = 0.f;

    float4 pxs[2][4];          // two X register sets (distance-2 prefetch)
    uint4 pqh, pql;            // Q set (L2-resident, distance-1)
    const int xrow0 = tid >> 3, xc4 = tid & 7;
    const int qrow = tid >> 2, qq = tid & 3;

    auto LDGX = [&](int c0, int s) {
        #pragma unroll
        for (int it = 0; it < 4; it++)
            pxs[s][it] = *reinterpret_cast<const float4*>(
                xb + (size_t)(xrow0 + it * 32) * HH + c0 + xc4 * 4);
    };
    auto LDGQ = [&](int c0) {
        if (tid < 192) {
            pqh = *reinterpret_cast<const uint4*>(qh + (size_t)qrow * HH + c0 + qq * 8);
            pql = *reinterpret_cast<const uint4*>(ql + (size_t)qrow * HH + c0 + qq * 8);
        }
    };
    auto STS = [&](int buf, int s) {
        char* xhb = dsm + buf * 10240;
        char* xlb = dsm + 20480 + buf * 10240;
        char* qhb = dsm + 40960 + buf * 3840;
        char* qlb = dsm + 48640 + buf * 3840;
        #pragma unroll
        for (int it = 0; it < 4; it++) {
            int row = xrow0 + it * 32;
            float4 v = pxs[s][it];
            *reinterpret_cast<uint2*>(xhb + (row * SXP + xc4 * 4) * 2) =
                make_uint2(pk2(v.x, v.y), pk2(v.z, v.w));
            *reinterpret_cast<uint2*>(xlb + (row * SXP + xc4 * 4) * 2) =
                make_uint2(pk2(rz(v.x), rz(v.y)), pk2(rz(v.z), rz(v.w)));
        }
        if (tid < 192) {
            *reinterpret_cast<uint4*>(qhb + (qrow * SXP + qq * 8) * 2) = pqh;
            *reinterpret_cast<uint4*>(qlb + (qrow * SXP + qq * 8) * 2) = pql;
        }
    };
    auto COMP = [&](int buf) {
        uint32_t uXh = ub + buf * 10240;
        uint32_t uXl = ub + 20480 + buf * 10240;
        uint32_t uQh = ub + 40960 + buf * 3840;
        uint32_t uQl = ub + 48640 + buf * 3840;
        #pragma unroll
        for (int ks = 0; ks < 2; ks++) {
            const int k0 = ks * 16;
            uint32_t aoff = ((w * 16 + (l & 15)) * SXP + k0 + ((l >> 4) << 3)) * 2;
            uint32_t ah[4], al[4];
            ldsm4(ah, uXh + aoff);
            ldsm4(al, uXl + aoff);
            #pragma unroll
            for (int ntp = 0; ntp < 3; ntp++) {
                uint32_t boff = ((ntp * 16 + ((l >> 4) << 3) + (l & 7)) * SXP + k0 + (l & 8)) * 2;
                uint32_t bh[4], bl[4];
                ldsm4(bh, uQh + boff);
                ldsm4(bl, uQl + boff);
                mma_bf16(acc[ntp * 2],     ah, bh[0], bh[1]);
                mma_bf16(acc[ntp * 2],     ah, bl[0], bl[1]);
                mma_bf16(acc[ntp * 2],     al, bh[0], bh[1]);
                mma_bf16(acc[ntp * 2 + 1], ah, bh[2], bh[3]);
                mma_bf16(acc[ntp * 2 + 1], ah, bl[2], bl[3]);
                mma_bf16(acc[ntp * 2 + 1], al, bh[2], bh[3]);
            }
        }
    };

    // prologue: X chunks 0 and 1 in flight; Q chunk 0; stage chunk 0
    LDGX(0, 0);
    LDGQ(0);
    LDGX(32, 1);
    STS(0, 0);
    __syncthreads();
    for (int ch = 1; ch < 24; ch++) {
        if (ch < 23) LDGX((ch + 1) * 32, (ch + 1) & 1);   // distance-2 prefetch
        LDGQ(ch * 32);
        COMP((ch - 1) & 1);
        STS(ch & 1, ch & 1);
        __syncthreads();
    }
    COMP(1);
    __syncthreads();

    float* stage = reinterpret_cast<float*>(dsm);
    {
        int yl = w * 16 + (l >> 2);
        #pragma unroll
        for (int nt = 0; nt < 6; nt++) {
            int r = nt * 8 + (l & 3) * 2;
            stage[r * 136 + yl]           = acc[nt][0];
            stage[(r + 1) * 136 + yl]     = acc[nt][1];
            stage[r * 136 + yl + 8]       = acc[nt][2];
            stage[(r + 1) * 136 + yl + 8] = acc[nt][3];
        }
    }
    __syncthreads();
    float* ob = g_sc + (size_t)b * RR * SS;
    #pragma unroll
    for (int i = tid; i < 48 * 32; i += 256) {
        int r = i >> 5, c4 = i & 31;
        float4 v = *reinterpret_cast<float4*>(&stage[r * 136 + c4 * 4]);
        *reinterpret_cast<float4*>(ob + (size_t)r * SS + y0 + c4 * 4) = v;
    }
}

// =================== Kernel 3: softmax -> bf16 hi/lo ===================
__global__ void __launch_bounds__(256) k_softmax() {
    const int row = blockIdx.x;
    const float* p = g_sc + (size_t)row * SS;
    __nv_bfloat16* oh = g_ath + (size_t)row * SS;
    __nv_bfloat16* ol = g_atl + (size_t)row * SS;
    __shared__ float sv[SS];
    __shared__ float red[8];

    float mx = -1e30f;
    for (int t = threadIdx.x; t < SS / 4; t += 256) {
        float4 v = reinterpret_cast<const float4*>(p)[t];
        reinterpret_cast<float4*>(sv)[t] = v;
        mx = fmaxf(mx, fmaxf(fmaxf(v.x, v.y), fmaxf(v.z, v.w)));
    }
    #pragma unroll
    for (int o = 16; o; o >>= 1) mx = fmaxf(mx, __shfl_xor_sync(0xffffffffu, mx, o));
    if ((threadIdx.x & 31) == 0) red[threadIdx.x >> 5] = mx;
    __syncthreads();
    float m = red[0];
    #pragma unroll
    for (int k = 1; k < 8; k++) m = fmaxf(m, red[k]);
    __syncthreads();

    float sum = 0.f;
    for (int t = threadIdx.x; t < SS / 4; t += 256) {
        float4 v = reinterpret_cast<float4*>(sv)[t];
        v.x = expf(v.x - m); v.y = expf(v.y - m);
        v.z = expf(v.z - m); v.w = expf(v.w - m);
        reinterpret_cast<float4*>(sv)[t] = v;
        sum += v.x + v.y + v.z + v.w;
    }
    #pragma unroll
    for (int o = 16; o; o >>= 1) sum += __shfl_xor_sync(0xffffffffu, sum, o);
    if ((threadIdx.x & 31) == 0) red[threadIdx.x >> 5] = sum;
    __syncthreads();
    float tot = 0.f;
    #pragma unroll
    for (int k = 0; k < 8; k++) tot += red[k];
    float inv = 1.0f / tot;

    for (int t = threadIdx.x; t < SS / 4; t += 256) {
        float4 v = reinterpret_cast<float4*>(sv)[t];
        v.x *= inv; v.y *= inv; v.z *= inv; v.w *= inv;
        reinterpret_cast<uint2*>(oh)[t] = make_uint2(pk2(v.x, v.y), pk2(v.z, v.w));
        reinterpret_cast<uint2*>(ol)[t] = make_uint2(pk2(rz(v.x), rz(v.y)), pk2(rz(v.z), rz(v.w)));
    }
}

// =========== Kernel 4 (ncu slot): ctx, distance-2 X prefetch ===========
#define CXP 72
#define CX_TOT 64512
__global__ void __launch_bounds__(192) k_ctx_mma(const float* __restrict__ x) {
    extern __shared__ __align__(16) char dsm[];
    const uint32_t ub = smem_u32(dsm);

    const int tid = threadIdx.x, w = tid >> 5, l = tid & 31;
    const int ct = blockIdx.x;
    const int sp = blockIdx.y;
    const int b  = blockIdx.z;
    const int c0 = ct * 64;
    const int ybase = sp * (SS / NSPLIT);   // 512 y per split

    const float* xb = x + (size_t)b * SS * HH + c0;
    const __nv_bfloat16* ah = g_ath + (size_t)b * RR * SS;
    const __nv_bfloat16* al = g_atl + (size_t)b * RR * SS;

    const int mt = w >> 1;
    const int cbase = (w & 1) * 32;

    float acc[4][4];
    #pragma unroll
    for (int n = 0; n < 4; n++)
        #pragma unroll
        for (int k = 0; k < 4; k++) acc[n][k] = 0.f;

    float4 pxs[2][6];          // two X register sets
    uint4 pah[2], pal[2];      // A set (L2-resident, distance-1)

    auto LDGX = [&](int yc, int s) {
        #pragma unroll
        for (int it = 0; it < 6; it++) {
            int t = tid + 192 * it;
            if (t < 1024) {
                int row = t >> 4, c4 = t & 15;
                pxs[s][it] = *reinterpret_cast<const float4*>(
                    xb + (size_t)(yc + row) * HH + c4 * 4);
            }
        }
    };
    auto LDGA = [&](int yc) {
        #pragma unroll
        for (int it = 0; it < 2; it++) {
            int t = tid + 192 * it;
            if (t < 384) {
                int row = t >> 3, q = t & 7;
                pah[it] = *reinterpret_cast<const uint4*>(ah + (size_t)row * SS + yc + q * 8);
                pal[it] = *reinterpret_cast<const uint4*>(al + (size_t)row * SS + yc + q * 8);
            }
        }
    };
    auto STS = [&](int buf, int s) {
        char* ahb = dsm + buf * 6912;
        char* alb = dsm + 13824 + buf * 6912;
        char* xhb = dsm + 27648 + buf * 9216;
        char* xlb = dsm + 46080 + buf * 9216;
        #pragma unroll
        for (int it = 0; it < 6; it++) {
            int t = tid + 192 * it;
            if (t < 1024) {
                int row = t >> 4, c4 = t & 15;
                float4 v = pxs[s][it];
                *reinterpret_cast<uint2*>(xhb + (row * CXP + c4 * 4) * 2) =
                    make_uint2(pk2(v.x, v.y), pk2(v.z, v.w));
                *reinterpret_cast<uint2*>(xlb + (row * CXP + c4 * 4) * 2) =
                    make_uint2(pk2(rz(v.x), rz(v.y)), pk2(rz(v.z), rz(v.w)));
            }
        }
        #pragma unroll
        for (int it = 0; it < 2; it++) {
            int t = tid + 192 * it;
            if (t < 384) {
                int row = t >> 3, q = t & 7;
                *reinterpret_cast<uint4*>(ahb + (row * CXP + q * 8) * 2) = pah[it];
                *reinterpret_cast<uint4*>(alb + (row * CXP + q * 8) * 2) = pal[it];
            }
        }
    };
    auto COMP = [&](int buf) {
        uint32_t uAh = ub + buf * 6912;
        uint32_t uAl = ub + 13824 + buf * 6912;
        uint32_t uXh = ub + 27648 + buf * 9216;
        uint32_t uXl = ub + 46080 + buf * 9216;
        #pragma unroll
        for (int ks = 0; ks < 4; ks++) {
            const int k0 = ks * 16;
            uint32_t aoff = ((mt * 16 + (l & 15)) * CXP + k0 + ((l >> 4) << 3)) * 2;
            uint32_t fa_h[4], fa_l[4];
            ldsm4(fa_h, uAh + aoff);
            ldsm4(fa_l, uAl + aoff);
            #pragma unroll
            for (int ntp = 0; ntp < 2; ntp++) {
                uint32_t boff = ((k0 + (l & 15)) * CXP + cbase + ntp * 16 + ((l >> 4) << 3)) * 2;
                uint32_t fb_h[4], fb_l[4];
                ldsm4t(fb_h, uXh + boff);
                ldsm4t(fb_l, uXl + boff);
                mma_bf16(acc[ntp * 2],     fa_h, fb_h[0], fb_h[1]);
                mma_bf16(acc[ntp * 2],     fa_h, fb_l[0], fb_l[1]);
                mma_bf16(acc[ntp * 2],     fa_l, fb_h[0], fb_h[1]);
                mma_bf16(acc[ntp * 2 + 1], fa_h, fb_h[2], fb_h[3]);
                mma_bf16(acc[ntp * 2 + 1], fa_h, fb_l[2], fb_l[3]);
                mma_bf16(acc[ntp * 2 + 1], fa_l, fb_h[2], fb_h[3]);
            }
        }
    };

    const int NCH = (SS / NSPLIT) / 64;   // 8 chunks
    LDGX(ybase, 0);
    LDGA(ybase);
    LDGX(ybase + 64, 1);
    STS(0, 0);
    __syncthreads();
    for (int ch = 1; ch < NCH; ch++) {
        if (ch < NCH - 1) LDGX(ybase + (ch + 1) * 64, (ch + 1) & 1);
        LDGA(ybase + ch * 64);
        COMP((ch - 1) & 1);
        STS(ch & 1, ch & 1);
        __syncthreads();
    }
    COMP((NCH - 1) & 1);

    float* ob = g_part + (size_t)((b * NSPLIT + sp) * RR) * HH + c0;
    int r0 = mt * 16 + (l >> 2);
    #pragma unroll
    for (int nt = 0; nt < 4; nt++) {
        int c = cbase + nt * 8 + (l & 3) * 2;
        *reinterpret_cast<float2*>(ob + (size_t)r0 * HH + c)       = make_float2(acc[nt][0], acc[nt][1]);
        *reinterpret_cast<float2*>(ob + (size_t)(r0 + 8) * HH + c) = make_float2(acc[nt][2], acc[nt][3]);
    }
}

// ==== Kernel 5: out1 with inline split-K reduction.  o = (Σ_sp part)·W_v ====
__global__ void __launch_bounds__(256) k_out1(const float* __restrict__ wkv) {
    int bt = blockIdx.x;
    int b = bt >> 2, t = bt & 3;
    int e0 = blockIdx.y * 128;
    __shared__ float sc_[2][HH];
    for (int idx = threadIdx.x; idx < 2 * HH / 4; idx += 256) {
        int hh = idx / (HH / 4), c4 = idx % (HH / 4);
        int h = (e0 >> 6) + hh;
        int r = h * NBN + t;
        float4 acc = make_float4(0.f, 0.f, 0.f, 0.f);
        #pragma unroll
        for (int sp = 0; sp < NSPLIT; sp++) {
            const float4* p = reinterpret_cast<const float4*>(
                g_part + ((size_t)((b * NSPLIT + sp) * RR) + r) * HH);
            float4 v = p[c4];
            acc.x += v.x; acc.y += v.y; acc.z += v.z; acc.w += v.w;
        }
        reinterpret_cast<float4*>(&sc_[hh][0])[c4] = acc;
    }
    __syncthreads();
    int e = e0 + (threadIdx.x >> 1);
    int half = threadIdx.x & 1;
    const float4* wr = reinterpret_cast<const float4*>(wkv + (size_t)(HH + e) * HH) + half * 96;
    const float4* cr = reinterpret_cast<const float4*>(&sc_[(e - e0) >> 6][0]) + half * 96;
    float a = 0.f;
    #pragma unroll 4
    for (int c4 = 0; c4 < 96; c4++) {
        float4 wv = wr[c4], cv = cr[c4];
        a += wv.x * cv.x + wv.y * cv.y + wv.z * cv.z + wv.w * cv.w;
    }
    a += __shfl_xor_sync(0xffffffffu, a, 1);
    if (half == 0) g_o[(size_t)bt * HH + e] = a;
}

// ========== Kernel 6: out[b,t,j] = g_o[b,t,:] · wout[j,:] + bout[j] ==========
__global__ void __launch_bounds__(256) k_out2(const float* __restrict__ wout,
                                              const float* __restrict__ bout,
                                              float* __restrict__ out) {
    int bt = blockIdx.x;
    int j0 = blockIdx.y * 128;
    __shared__ float so[HH];
    for (int idx = threadIdx.x; idx < HH / 4; idx += 256)
        reinterpret_cast<float4*>(so)[idx] =
            reinterpret_cast<const float4*>(g_o + (size_t)bt * HH)[idx];
    __syncthreads();
    int j = j0 + (threadIdx.x >> 1);
    int half = threadIdx.x & 1;
    const float4* wr = reinterpret_cast<const float4*>(wout + (size_t)j * HH) + half * 96;
    const float4* sr = reinterpret_cast<const float4*>(so) + half * 96;
    float a = 0.f;
    #pragma unroll 4
    for (int c4 = 0; c4 < 96; c4++) {
        float4 wv = wr[c4], sv = sr[c4];
        a += wv.x * sv.x + wv.y * sv.y + wv.z * sv.z + wv.w * sv.w;
    }
    a += __shfl_xor_sync(0xffffffffu, a, 1);
    if (half == 0) out[(size_t)bt * HH + j] = a + bout[j];
}

// ---------------------------------------------------------------------------
extern "C" void kernel_launch(void* const* d_in, const int* in_sizes, int n_in,
                              void* d_out, int out_size) {
    const float* x    = (const float*)d_in[0];
    const float* wkv  = (const float*)d_in[1];
    const float* wq   = (const float*)d_in[2];
    const float* wout = (const float*)d_in[3];
    const float* bout = (const float*)d_in[4];
    float* out = (float*)d_out;

    cudaFuncSetAttribute(k_scores_mma, cudaFuncAttributeMaxDynamicSharedMemorySize, SC_TOT);
    cudaFuncSetAttribute(k_ctx_mma,    cudaFuncAttributeMaxDynamicSharedMemorySize, CX_TOT);

    k_qw<<<dim3(3, BB * NH), 256>>>(x, wq, wkv);                 // 1
    k_scores_mma<<<dim3(SS / 128, BB), 256, SC_TOT>>>(x);        // 2
    k_softmax<<<BB * RR, 256>>>();                               // 3
    k_ctx_mma<<<dim3(HH / 64, NSPLIT, BB), 192, CX_TOT>>>(x);    // 4 (ncu slot)
    k_out1<<<dim3(BB * NBN, HH / 128), 256>>>(wkv);              // 5
    k_out2<<<dim3(BB * NBN, HH / 128), 256>>>(wout, bout, out);  // 6
}

// round 16
// speedup vs baseline: 1.7669x; 1.7669x over previous
#include <cuda_runtime.h>
#include <cuda_bf16.h>
#include <cstdint>
#include <math.h>

#define BB 8
#define SS 8192
#define HH 768
#define NH 12
#define HD 64
#define NBN 4
#define RR 48
#define SCALEF 0.125f
#define NSPLIT 16

// ---------------- global scratch ----------------
__device__ __nv_bfloat16 g_qwh[BB*RR*HH];
__device__ __nv_bfloat16 g_qwl[BB*RR*HH];
__device__ float g_sc[(size_t)BB*RR*SS];
__device__ __nv_bfloat16 g_ath[(size_t)BB*RR*SS];
__device__ __nv_bfloat16 g_atl[(size_t)BB*RR*SS];
__device__ float g_part[(size_t)BB*NSPLIT*RR*HH];
__device__ float g_o[BB*NBN*HH];

// ---------------- helpers ----------------
__device__ __forceinline__ uint32_t smem_u32(const void* p) {
    uint32_t a;
    asm("{ .reg .u64 t; cvta.to.shared.u64 t, %1; cvt.u32.u64 %0, t; }" : "=r"(a) : "l"(p));
    return a;
}
__device__ __forceinline__ void ldsm4(uint32_t* r, uint32_t a) {
    asm volatile("ldmatrix.sync.aligned.m8n8.x4.shared.b16 {%0,%1,%2,%3}, [%4];"
        : "=r"(r[0]), "=r"(r[1]), "=r"(r[2]), "=r"(r[3]) : "r"(a));
}
__device__ __forceinline__ void ldsm4t(uint32_t* r, uint32_t a) {
    asm volatile("ldmatrix.sync.aligned.m8n8.x4.trans.shared.b16 {%0,%1,%2,%3}, [%4];"
        : "=r"(r[0]), "=r"(r[1]), "=r"(r[2]), "=r"(r[3]) : "r"(a));
}
__device__ __forceinline__ void mma_bf16(float* c, const uint32_t* a, uint32_t b0, uint32_t b1) {
    asm volatile("mma.sync.aligned.m16n8k16.row.col.f32.bf16.bf16.f32 "
        "{%0,%1,%2,%3}, {%4,%5,%6,%7}, {%8,%9}, {%0,%1,%2,%3};"
        : "+f"(c[0]), "+f"(c[1]), "+f"(c[2]), "+f"(c[3])
        : "r"(a[0]), "r"(a[1]), "r"(a[2]), "r"(a[3]), "r"(b0), "r"(b1));
}
__device__ __forceinline__ uint32_t pk2(float a, float b) {
    __nv_bfloat162 t = __floats2bfloat162_rn(a, b);
    return *reinterpret_cast<uint32_t*>(&t);
}
__device__ __forceinline__ float rz(float v) {
    return v - __bfloat162float(__float2bfloat16_rn(v));
}

// ========== Kernel 1: qw projection, split over 3 c-chunks (288 CTAs) ==========
__global__ void __launch_bounds__(256) k_qw(const float* __restrict__ x,
                                            const float* __restrict__ wq,
                                            const float* __restrict__ wkv) {
    int cchunk = blockIdx.x;
    int b = blockIdx.y / NH, h = blockIdx.y % NH;
    __shared__ float sx[NBN][HH];
    __shared__ float sq[NBN][HD];
    for (int idx = threadIdx.x; idx < NBN * HH; idx += 256) {
        int t = idx / HH, c = idx % HH;
        sx[t][c] = x[((size_t)b * SS + t) * HH + c];
    }
    __syncthreads();
    {
        int d = threadIdx.x >> 2, s = threadIdx.x & 3;
        const float4* wr = reinterpret_cast<const float4*>(wq + (size_t)(h * HD + d) * HH);
        float a[NBN] = {0.f, 0.f, 0.f, 0.f};
        #pragma unroll 4
        for (int kk = 0; kk < 48; kk++) {
            int c4 = s + kk * 4;
            float4 wv = wr[c4];
            #pragma unroll
            for (int t = 0; t < NBN; t++) {
                float4 sv = reinterpret_cast<const float4*>(sx[t])[c4];
                a[t] += wv.x * sv.x + wv.y * sv.y + wv.z * sv.z + wv.w * sv.w;
            }
        }
        #pragma unroll
        for (int t = 0; t < NBN; t++) {
            a[t] += __shfl_xor_sync(0xffffffffu, a[t], 1);
            a[t] += __shfl_xor_sync(0xffffffffu, a[t], 2);
        }
        if (s == 0)
            #pragma unroll
            for (int t = 0; t < NBN; t++) sq[t][d] = a[t];
    }
    __syncthreads();
    {
        int c = cchunk * 256 + threadIdx.x;
        float a[NBN] = {0.f, 0.f, 0.f, 0.f};
        #pragma unroll 8
        for (int d = 0; d < HD; d++) {
            float wv = wkv[(size_t)(h * HD + d) * HH + c];
            #pragma unroll
            for (int t = 0; t < NBN; t++) a[t] += sq[t][d] * wv;
        }
        #pragma unroll
        for (int t = 0; t < NBN; t++) {
            float v = a[t] * SCALEF;
            size_t idx = (size_t)(b * RR + h * NBN + t) * HH + c;
            __nv_bfloat16 hi = __float2bfloat16_rn(v);
            g_qwh[idx] = hi;
            g_qwl[idx] = __float2bfloat16_rn(v - __bfloat162float(hi));
        }
    }
}

// =========== Kernel 2: scores (exact R11 form; measured 79.6 us) ===========
#define SXP 40
#define SC_TOT 56320
__global__ void __launch_bounds__(256) k_scores_mma(const float* __restrict__ x) {
    extern __shared__ __align__(16) char dsm[];
    const uint32_t ub = smem_u32(dsm);

    const int tid = threadIdx.x, w = tid >> 5, l = tid & 31;
    const int b = blockIdx.y;
    const int y0 = blockIdx.x * 128;

    const float* xb = x + ((size_t)b * SS + y0) * HH;
    const __nv_bfloat16* qh = g_qwh + (size_t)b * RR * HH;
    const __nv_bfloat16* ql = g_qwl + (size_t)b * RR * HH;

    float acc[6][4];
    #pragma unroll
    for (int n = 0; n < 6; n++)
        #pragma unroll
        for (int k = 0; k < 4; k++) acc[n][k] = 0.f;

    float4 px[4];
    uint4 pqh, pql;
    const int xrow0 = tid >> 3, xc4 = tid & 7;
    const int qrow = tid >> 2, qq = tid & 3;

    auto LDG = [&](int c0) {
        #pragma unroll
        for (int it = 0; it < 4; it++)
            px[it] = *reinterpret_cast<const float4*>(
                xb + (size_t)(xrow0 + it * 32) * HH + c0 + xc4 * 4);
        if (tid < 192) {
            pqh = *reinterpret_cast<const uint4*>(qh + (size_t)qrow * HH + c0 + qq * 8);
            pql = *reinterpret_cast<const uint4*>(ql + (size_t)qrow * HH + c0 + qq * 8);
        }
    };
    auto STS = [&](int buf) {
        char* xhb = dsm + buf * 10240;
        char* xlb = dsm + 20480 + buf * 10240;
        char* qhb = dsm + 40960 + buf * 3840;
        char* qlb = dsm + 48640 + buf * 3840;
        #pragma unroll
        for (int it = 0; it < 4; it++) {
            int row = xrow0 + it * 32;
            float4 v = px[it];
            *reinterpret_cast<uint2*>(xhb + (row * SXP + xc4 * 4) * 2) =
                make_uint2(pk2(v.x, v.y), pk2(v.z, v.w));
            *reinterpret_cast<uint2*>(xlb + (row * SXP + xc4 * 4) * 2) =
                make_uint2(pk2(rz(v.x), rz(v.y)), pk2(rz(v.z), rz(v.w)));
        }
        if (tid < 192) {
            *reinterpret_cast<uint4*>(qhb + (qrow * SXP + qq * 8) * 2) = pqh;
            *reinterpret_cast<uint4*>(qlb + (qrow * SXP + qq * 8) * 2) = pql;
        }
    };
    auto COMP = [&](int buf) {
        uint32_t uXh = ub + buf * 10240;
        uint32_t uXl = ub + 20480 + buf * 10240;
        uint32_t uQh = ub + 40960 + buf * 3840;
        uint32_t uQl = ub + 48640 + buf * 3840;
        #pragma unroll
        for (int ks = 0; ks < 2; ks++) {
            const int k0 = ks * 16;
            uint32_t aoff = ((w * 16 + (l & 15)) * SXP + k0 + ((l >> 4) << 3)) * 2;
            uint32_t ah[4], al[4];
            ldsm4(ah, uXh + aoff);
            ldsm4(al, uXl + aoff);
            #pragma unroll
            for (int ntp = 0; ntp < 3; ntp++) {
                uint32_t boff = ((ntp * 16 + ((l >> 4) << 3) + (l & 7)) * SXP + k0 + (l & 8)) * 2;
                uint32_t bh[4], bl[4];
                ldsm4(bh, uQh + boff);
                ldsm4(bl, uQl + boff);
                mma_bf16(acc[ntp * 2],     ah, bh[0], bh[1]);
                mma_bf16(acc[ntp * 2],     ah, bl[0], bl[1]);
                mma_bf16(acc[ntp * 2],     al, bh[0], bh[1]);
                mma_bf16(acc[ntp * 2 + 1], ah, bh[2], bh[3]);
                mma_bf16(acc[ntp * 2 + 1], ah, bl[2], bl[3]);
                mma_bf16(acc[ntp * 2 + 1], al, bh[2], bh[3]);
            }
        }
    };

    LDG(0);
    STS(0);
    __syncthreads();
    for (int ch = 1; ch < 24; ch++) {
        LDG(ch * 32);
        COMP((ch - 1) & 1);
        STS(ch & 1);
        __syncthreads();
    }
    COMP(23 & 1);
    __syncthreads();

    float* stage = reinterpret_cast<float*>(dsm);
    {
        int yl = w * 16 + (l >> 2);
        #pragma unroll
        for (int nt = 0; nt < 6; nt++) {
            int r = nt * 8 + (l & 3) * 2;
            stage[r * 136 + yl]           = acc[nt][0];
            stage[(r + 1) * 136 + yl]     = acc[nt][1];
            stage[r * 136 + yl + 8]       = acc[nt][2];
            stage[(r + 1) * 136 + yl + 8] = acc[nt][3];
        }
    }
    __syncthreads();
    float* ob = g_sc + (size_t)b * RR * SS;
    #pragma unroll
    for (int i = tid; i < 48 * 32; i += 256) {
        int r = i >> 5, c4 = i & 31;
        float4 v = *reinterpret_cast<float4*>(&stage[r * 136 + c4 * 4]);
        *reinterpret_cast<float4*>(ob + (size_t)r * SS + y0 + c4 * 4) = v;
    }
}

// =================== Kernel 3: softmax -> bf16 hi/lo ===================
__global__ void __launch_bounds__(256) k_softmax() {
    const int row = blockIdx.x;
    const float* p = g_sc + (size_t)row * SS;
    __nv_bfloat16* oh = g_ath + (size_t)row * SS;
    __nv_bfloat16* ol = g_atl + (size_t)row * SS;
    __shared__ float sv[SS];
    __shared__ float red[8];

    float mx = -1e30f;
    for (int t = threadIdx.x; t < SS / 4; t += 256) {
        float4 v = reinterpret_cast<const float4*>(p)[t];
        reinterpret_cast<float4*>(sv)[t] = v;
        mx = fmaxf(mx, fmaxf(fmaxf(v.x, v.y), fmaxf(v.z, v.w)));
    }
    #pragma unroll
    for (int o = 16; o; o >>= 1) mx = fmaxf(mx, __shfl_xor_sync(0xffffffffu, mx, o));
    if ((threadIdx.x & 31) == 0) red[threadIdx.x >> 5] = mx;
    __syncthreads();
    float m = red[0];
    #pragma unroll
    for (int k = 1; k < 8; k++) m = fmaxf(m, red[k]);
    __syncthreads();

    float sum = 0.f;
    for (int t = threadIdx.x; t < SS / 4; t += 256) {
        float4 v = reinterpret_cast<float4*>(sv)[t];
        v.x = expf(v.x - m); v.y = expf(v.y - m);
        v.z = expf(v.z - m); v.w = expf(v.w - m);
        reinterpret_cast<float4*>(sv)[t] = v;
        sum += v.x + v.y + v.z + v.w;
    }
    #pragma unroll
    for (int o = 16; o; o >>= 1) sum += __shfl_xor_sync(0xffffffffu, sum, o);
    if ((threadIdx.x & 31) == 0) red[threadIdx.x >> 5] = sum;
    __syncthreads();
    float tot = 0.f;
    #pragma unroll
    for (int k = 0; k < 8; k++) tot += red[k];
    float inv = 1.0f / tot;

    for (int t = threadIdx.x; t < SS / 4; t += 256) {
        float4 v = reinterpret_cast<float4*>(sv)[t];
        v.x *= inv; v.y *= inv; v.z *= inv; v.w *= inv;
        reinterpret_cast<uint2*>(oh)[t] = make_uint2(pk2(v.x, v.y), pk2(v.z, v.w));
        reinterpret_cast<uint2*>(ol)[t] = make_uint2(pk2(rz(v.x), rz(v.y)), pk2(rz(v.z), rz(v.w)));
    }
}

// =========== Kernel 4 (ncu slot): ctx (exact R11 form; measured 77.3 us) ===========
#define CXP 72
#define CX_TOT 64512
__global__ void __launch_bounds__(192) k_ctx_mma(const float* __restrict__ x) {
    extern __shared__ __align__(16) char dsm[];
    const uint32_t ub = smem_u32(dsm);

    const int tid = threadIdx.x, w = tid >> 5, l = tid & 31;
    const int ct = blockIdx.x;
    const int sp = blockIdx.y;
    const int b  = blockIdx.z;
    const int c0 = ct * 64;
    const int ybase = sp * (SS / NSPLIT);   // 512 y per split

    const float* xb = x + (size_t)b * SS * HH + c0;
    const __nv_bfloat16* ah = g_ath + (size_t)b * RR * SS;
    const __nv_bfloat16* al = g_atl + (size_t)b * RR * SS;

    const int mt = w >> 1;
    const int cbase = (w & 1) * 32;

    float acc[4][4];
    #pragma unroll
    for (int n = 0; n < 4; n++)
        #pragma unroll
        for (int k = 0; k < 4; k++) acc[n][k] = 0.f;

    float4 px[6];
    uint4 pah[2], pal[2];

    auto LDG = [&](int yc) {
        #pragma unroll
        for (int it = 0; it < 6; it++) {
            int t = tid + 192 * it;
            if (t < 1024) {
                int row = t >> 4, c4 = t & 15;
                px[it] = *reinterpret_cast<const float4*>(
                    xb + (size_t)(yc + row) * HH + c4 * 4);
            }
        }
        #pragma unroll
        for (int it = 0; it < 2; it++) {
            int t = tid + 192 * it;
            if (t < 384) {
                int row = t >> 3, q = t & 7;
                pah[it] = *reinterpret_cast<const uint4*>(ah + (size_t)row * SS + yc + q * 8);
                pal[it] = *reinterpret_cast<const uint4*>(al + (size_t)row * SS + yc + q * 8);
            }
        }
    };
    auto STS = [&](int buf) {
        char* ahb = dsm + buf * 6912;
        char* alb = dsm + 13824 + buf * 6912;
        char* xhb = dsm + 27648 + buf * 9216;
        char* xlb = dsm + 46080 + buf * 9216;
        #pragma unroll
        for (int it = 0; it < 6; it++) {
            int t = tid + 192 * it;
            if (t < 1024) {
                int row = t >> 4, c4 = t & 15;
                float4 v = px[it];
                *reinterpret_cast<uint2*>(xhb + (row * CXP + c4 * 4) * 2) =
                    make_uint2(pk2(v.x, v.y), pk2(v.z, v.w));
                *reinterpret_cast<uint2*>(xlb + (row * CXP + c4 * 4) * 2) =
                    make_uint2(pk2(rz(v.x), rz(v.y)), pk2(rz(v.z), rz(v.w)));
            }
        }
        #pragma unroll
        for (int it = 0; it < 2; it++) {
            int t = tid + 192 * it;
            if (t < 384) {
                int row = t >> 3, q = t & 7;
                *reinterpret_cast<uint4*>(ahb + (row * CXP + q * 8) * 2) = pah[it];
                *reinterpret_cast<uint4*>(alb + (row * CXP + q * 8) * 2) = pal[it];
            }
        }
    };
    auto COMP = [&](int buf) {
        uint32_t uAh = ub + buf * 6912;
        uint32_t uAl = ub + 13824 + buf * 6912;
        uint32_t uXh = ub + 27648 + buf * 9216;
        uint32_t uXl = ub + 46080 + buf * 9216;
        #pragma unroll
        for (int ks = 0; ks < 4; ks++) {
            const int k0 = ks * 16;
            uint32_t aoff = ((mt * 16 + (l & 15)) * CXP + k0 + ((l >> 4) << 3)) * 2;
            uint32_t fa_h[4], fa_l[4];
            ldsm4(fa_h, uAh + aoff);
            ldsm4(fa_l, uAl + aoff);
            #pragma unroll
            for (int ntp = 0; ntp < 2; ntp++) {
                uint32_t boff = ((k0 + (l & 15)) * CXP + cbase + ntp * 16 + ((l >> 4) << 3)) * 2;
                uint32_t fb_h[4], fb_l[4];
                ldsm4t(fb_h, uXh + boff);
                ldsm4t(fb_l, uXl + boff);
                mma_bf16(acc[ntp * 2],     fa_h, fb_h[0], fb_h[1]);
                mma_bf16(acc[ntp * 2],     fa_h, fb_l[0], fb_l[1]);
                mma_bf16(acc[ntp * 2],     fa_l, fb_h[0], fb_h[1]);
                mma_bf16(acc[ntp * 2 + 1], fa_h, fb_h[2], fb_h[3]);
                mma_bf16(acc[ntp * 2 + 1], fa_h, fb_l[2], fb_l[3]);
                mma_bf16(acc[ntp * 2 + 1], fa_l, fb_h[2], fb_h[3]);
            }
        }
    };

    const int NCH = (SS / NSPLIT) / 64;   // 8 chunks
    LDG(ybase);
    STS(0);
    __syncthreads();
    for (int ch = 1; ch < NCH; ch++) {
        LDG(ybase + ch * 64);
        COMP((ch - 1) & 1);
        STS(ch & 1);
        __syncthreads();
    }
    COMP((NCH - 1) & 1);

    float* ob = g_part + (size_t)((b * NSPLIT + sp) * RR) * HH + c0;
    int r0 = mt * 16 + (l >> 2);
    #pragma unroll
    for (int nt = 0; nt < 4; nt++) {
        int c = cbase + nt * 8 + (l & 3) * 2;
        *reinterpret_cast<float2*>(ob + (size_t)r0 * HH + c)       = make_float2(acc[nt][0], acc[nt][1]);
        *reinterpret_cast<float2*>(ob + (size_t)(r0 + 8) * HH + c) = make_float2(acc[nt][2], acc[nt][3]);
    }
}

// ==== Kernel 5: out1 with inline split-K reduction.  o = (Σ_sp part)·W_v ====
__global__ void __launch_bounds__(256) k_out1(const float* __restrict__ wkv) {
    int bt = blockIdx.x;
    int b = bt >> 2, t = bt & 3;
    int e0 = blockIdx.y * 128;
    __shared__ float sc_[2][HH];
    for (int idx = threadIdx.x; idx < 2 * HH / 4; idx += 256) {
        int hh = idx / (HH / 4), c4 = idx % (HH / 4);
        int h = (e0 >> 6) + hh;
        int r = h * NBN + t;
        float4 acc = make_float4(0.f, 0.f, 0.f, 0.f);
        #pragma unroll
        for (int sp = 0; sp < NSPLIT; sp++) {
            const float4* p = reinterpret_cast<const float4*>(
                g_part + ((size_t)((b * NSPLIT + sp) * RR) + r) * HH);
            float4 v = p[c4];
            acc.x += v.x; acc.y += v.y; acc.z += v.z; acc.w += v.w;
        }
        reinterpret_cast<float4*>(&sc_[hh][0])[c4] = acc;
    }
    __syncthreads();
    int e = e0 + (threadIdx.x >> 1);
    int half = threadIdx.x & 1;
    const float4* wr = reinterpret_cast<const float4*>(wkv + (size_t)(HH + e) * HH) + half * 96;
    const float4* cr = reinterpret_cast<const float4*>(&sc_[(e - e0) >> 6][0]) + half * 96;
    float a = 0.f;
    #pragma unroll 4
    for (int c4 = 0; c4 < 96; c4++) {
        float4 wv = wr[c4], cv = cr[c4];
        a += wv.x * cv.x + wv.y * cv.y + wv.z * cv.z + wv.w * cv.w;
    }
    a += __shfl_xor_sync(0xffffffffu, a, 1);
    if (half == 0) g_o[(size_t)bt * HH + e] = a;
}

// ========== Kernel 6: out[b,t,j] = g_o[b,t,:] · wout[j,:] + bout[j] ==========
__global__ void __launch_bounds__(256) k_out2(const float* __restrict__ wout,
                                              const float* __restrict__ bout,
                                              float* __restrict__ out) {
    int bt = blockIdx.x;
    int j0 = blockIdx.y * 128;
    __shared__ float so[HH];
    for (int idx = threadIdx.x; idx < HH / 4; idx += 256)
        reinterpret_cast<float4*>(so)[idx] =
            reinterpret_cast<const float4*>(g_o + (size_t)bt * HH)[idx];
    __syncthreads();
    int j = j0 + (threadIdx.x >> 1);
    int half = threadIdx.x & 1;
    const float4* wr = reinterpret_cast<const float4*>(wout + (size_t)j * HH) + half * 96;
    const float4* sr = reinterpret_cast<const float4*>(so) + half * 96;
    float a = 0.f;
    #pragma unroll 4
    for (int c4 = 0; c4 < 96; c4++) {
        float4 wv = wr[c4], sv = sr[c4];
        a += wv.x * sv.x + wv.y * sv.y + wv.z * sv.z + wv.w * sv.w;
    }
    a += __shfl_xor_sync(0xffffffffu, a, 1);
    if (half == 0) out[(size_t)bt * HH + j] = a + bout[j];
}

// ---------------------------------------------------------------------------
extern "C" void kernel_launch(void* const* d_in, const int* in_sizes, int n_in,
                              void* d_out, int out_size) {
    const float* x    = (const float*)d_in[0];
    const float* wkv  = (const float*)d_in[1];
    const float* wq   = (const float*)d_in[2];
    const float* wout = (const float*)d_in[3];
    const float* bout = (const float*)d_in[4];
    float* out = (float*)d_out;

    cudaFuncSetAttribute(k_scores_mma, cudaFuncAttributeMaxDynamicSharedMemorySize, SC_TOT);
    cudaFuncSetAttribute(k_ctx_mma,    cudaFuncAttributeMaxDynamicSharedMemorySize, CX_TOT);

    k_qw<<<dim3(3, BB * NH), 256>>>(x, wq, wkv);                 // 1
    k_scores_mma<<<dim3(SS / 128, BB), 256, SC_TOT>>>(x);        // 2
    k_softmax<<<BB * RR, 256>>>();                               // 3
    k_ctx_mma<<<dim3(HH / 64, NSPLIT, BB), 192, CX_TOT>>>(x);    // 4 (ncu slot)
    k_out1<<<dim3(BB * NBN, HH / 128), 256>>>(wkv);              // 5
    k_out2<<<dim3(BB * NBN, HH / 128), 256>>>(wout, bout, out);  // 6
}

// round 17
// speedup vs baseline: 1.7850x; 1.0102x over previous
#include <cuda_runtime.h>
#include <cuda_bf16.h>
#include <cstdint>
#include <math.h>

#define BB 8
#define SS 8192
#define HH 768
#define NH 12
#define HD 64
#define NBN 4
#define RR 48
#define SCALEF 0.125f
#define NSPLIT 16

// ---------------- global scratch ----------------
__device__ __nv_bfloat16 g_qwh[BB*RR*HH];
__device__ __nv_bfloat16 g_qwl[BB*RR*HH];
__device__ float g_sc[(size_t)BB*RR*SS];
__device__ __nv_bfloat16 g_ath[(size_t)BB*RR*SS];
__device__ __nv_bfloat16 g_atl[(size_t)BB*RR*SS];
__device__ float g_part[(size_t)BB*NSPLIT*RR*HH];
__device__ float g_ctx[BB*RR*HH];
__device__ float g_o[BB*NBN*HH];

// ---------------- helpers ----------------
__device__ __forceinline__ uint32_t smem_u32(const void* p) {
    uint32_t a;
    asm("{ .reg .u64 t; cvta.to.shared.u64 t, %1; cvt.u32.u64 %0, t; }" : "=r"(a) : "l"(p));
    return a;
}
__device__ __forceinline__ void ldsm4(uint32_t* r, uint32_t a) {
    asm volatile("ldmatrix.sync.aligned.m8n8.x4.shared.b16 {%0,%1,%2,%3}, [%4];"
        : "=r"(r[0]), "=r"(r[1]), "=r"(r[2]), "=r"(r[3]) : "r"(a));
}
__device__ __forceinline__ void ldsm4t(uint32_t* r, uint32_t a) {
    asm volatile("ldmatrix.sync.aligned.m8n8.x4.trans.shared.b16 {%0,%1,%2,%3}, [%4];"
        : "=r"(r[0]), "=r"(r[1]), "=r"(r[2]), "=r"(r[3]) : "r"(a));
}
__device__ __forceinline__ void mma_bf16(float* c, const uint32_t* a, uint32_t b0, uint32_t b1) {
    asm volatile("mma.sync.aligned.m16n8k16.row.col.f32.bf16.bf16.f32 "
        "{%0,%1,%2,%3}, {%4,%5,%6,%7}, {%8,%9}, {%0,%1,%2,%3};"
        : "+f"(c[0]), "+f"(c[1]), "+f"(c[2]), "+f"(c[3])
        : "r"(a[0]), "r"(a[1]), "r"(a[2]), "r"(a[3]), "r"(b0), "r"(b1));
}
__device__ __forceinline__ uint32_t pk2(float a, float b) {
    __nv_bfloat162 t = __floats2bfloat162_rn(a, b);
    return *reinterpret_cast<uint32_t*>(&t);
}
__device__ __forceinline__ float rz(float v) {
    return v - __bfloat162float(__float2bfloat16_rn(v));
}

// ========== Kernel 1: qw projection, split over 3 c-chunks (288 CTAs) ==========
__global__ void __launch_bounds__(256) k_qw(const float* __restrict__ x,
                                            const float* __restrict__ wq,
                                            const float* __restrict__ wkv) {
    int cchunk = blockIdx.x;
    int b = blockIdx.y / NH, h = blockIdx.y % NH;
    __shared__ float sx[NBN][HH];
    __shared__ float sq[NBN][HD];
    for (int idx = threadIdx.x; idx < NBN * HH; idx += 256) {
        int t = idx / HH, c = idx % HH;
        sx[t][c] = x[((size_t)b * SS + t) * HH + c];
    }
    __syncthreads();
    {
        int d = threadIdx.x >> 2, s = threadIdx.x & 3;
        const float4* wr = reinterpret_cast<const float4*>(wq + (size_t)(h * HD + d) * HH);
        float a[NBN] = {0.f, 0.f, 0.f, 0.f};
        #pragma unroll 4
        for (int kk = 0; kk < 48; kk++) {
            int c4 = s + kk * 4;
            float4 wv = wr[c4];
            #pragma unroll
            for (int t = 0; t < NBN; t++) {
                float4 sv = reinterpret_cast<const float4*>(sx[t])[c4];
                a[t] += wv.x * sv.x + wv.y * sv.y + wv.z * sv.z + wv.w * sv.w;
            }
        }
        #pragma unroll
        for (int t = 0; t < NBN; t++) {
            a[t] += __shfl_xor_sync(0xffffffffu, a[t], 1);
            a[t] += __shfl_xor_sync(0xffffffffu, a[t], 2);
        }
        if (s == 0)
            #pragma unroll
            for (int t = 0; t < NBN; t++) sq[t][d] = a[t];
    }
    __syncthreads();
    {
        int c = cchunk * 256 + threadIdx.x;
        float a[NBN] = {0.f, 0.f, 0.f, 0.f};
        #pragma unroll 8
        for (int d = 0; d < HD; d++) {
            float wv = wkv[(size_t)(h * HD + d) * HH + c];
            #pragma unroll
            for (int t = 0; t < NBN; t++) a[t] += sq[t][d] * wv;
        }
        #pragma unroll
        for (int t = 0; t < NBN; t++) {
            float v = a[t] * SCALEF;
            size_t idx = (size_t)(b * RR + h * NBN + t) * HH + c;
            __nv_bfloat16 hi = __float2bfloat16_rn(v);
            g_qwh[idx] = hi;
            g_qwl[idx] = __float2bfloat16_rn(v - __bfloat162float(hi));
        }
    }
}

// ====== Kernel 2: scores, manual unroll-2 distance-2 X prefetch (named reg sets) ======
#define SXP 40
#define SC_TOT 56320
__global__ void __launch_bounds__(256) k_scores_mma(const float* __restrict__ x) {
    extern __shared__ __align__(16) char dsm[];
    const uint32_t ub = smem_u32(dsm);

    const int tid = threadIdx.x, w = tid >> 5, l = tid & 31;
    const int b = blockIdx.y;
    const int y0 = blockIdx.x * 128;

    const float* xb = x + ((size_t)b * SS + y0) * HH;
    const __nv_bfloat16* qh = g_qwh + (size_t)b * RR * HH;
    const __nv_bfloat16* ql = g_qwl + (size_t)b * RR * HH;

    float acc[6][4];
    #pragma unroll
    for (int n = 0; n < 6; n++)
        #pragma unroll
        for (int k = 0; k < 4; k++) acc[n][k] = 0.f;

    float4 pxA[4], pxB[4];      // two named X register sets (no dynamic indexing)
    uint4 pqh, pql;             // Q set (L2-resident, distance-1)
    const int xrow0 = tid >> 3, xc4 = tid & 7;
    const int qrow = tid >> 2, qq = tid & 3;

    auto LDGXA = [&](int c0) {
        #pragma unroll
        for (int it = 0; it < 4; it++)
            pxA[it] = *reinterpret_cast<const float4*>(
                xb + (size_t)(xrow0 + it * 32) * HH + c0 + xc4 * 4);
    };
    auto LDGXB = [&](int c0) {
        #pragma unroll
        for (int it = 0; it < 4; it++)
            pxB[it] = *reinterpret_cast<const float4*>(
                xb + (size_t)(xrow0 + it * 32) * HH + c0 + xc4 * 4);
    };
    auto LDGQ = [&](int c0) {
        if (tid < 192) {
            pqh = *reinterpret_cast<const uint4*>(qh + (size_t)qrow * HH + c0 + qq * 8);
            pql = *reinterpret_cast<const uint4*>(ql + (size_t)qrow * HH + c0 + qq * 8);
        }
    };
    auto STSQ = [&](int buf) {
        char* qhb = dsm + 40960 + buf * 3840;
        char* qlb = dsm + 48640 + buf * 3840;
        if (tid < 192) {
            *reinterpret_cast<uint4*>(qhb + (qrow * SXP + qq * 8) * 2) = pqh;
            *reinterpret_cast<uint4*>(qlb + (qrow * SXP + qq * 8) * 2) = pql;
        }
    };
    auto STSA = [&](int buf) {
        char* xhb = dsm + buf * 10240;
        char* xlb = dsm + 20480 + buf * 10240;
        #pragma unroll
        for (int it = 0; it < 4; it++) {
            int row = xrow0 + it * 32;
            float4 v = pxA[it];
            *reinterpret_cast<uint2*>(xhb + (row * SXP + xc4 * 4) * 2) =
                make_uint2(pk2(v.x, v.y), pk2(v.z, v.w));
            *reinterpret_cast<uint2*>(xlb + (row * SXP + xc4 * 4) * 2) =
                make_uint2(pk2(rz(v.x), rz(v.y)), pk2(rz(v.z), rz(v.w)));
        }
        STSQ(buf);
    };
    auto STSB = [&](int buf) {
        char* xhb = dsm + buf * 10240;
        char* xlb = dsm + 20480 + buf * 10240;
        #pragma unroll
        for (int it = 0; it < 4; it++) {
            int row = xrow0 + it * 32;
            float4 v = pxB[it];
            *reinterpret_cast<uint2*>(xhb + (row * SXP + xc4 * 4) * 2) =
                make_uint2(pk2(v.x, v.y), pk2(v.z, v.w));
            *reinterpret_cast<uint2*>(xlb + (row * SXP + xc4 * 4) * 2) =
                make_uint2(pk2(rz(v.x), rz(v.y)), pk2(rz(v.z), rz(v.w)));
        }
        STSQ(buf);
    };
    auto COMP = [&](int buf) {
        uint32_t uXh = ub + buf * 10240;
        uint32_t uXl = ub + 20480 + buf * 10240;
        uint32_t uQh = ub + 40960 + buf * 3840;
        uint32_t uQl = ub + 48640 + buf * 3840;
        #pragma unroll
        for (int ks = 0; ks < 2; ks++) {
            const int k0 = ks * 16;
            uint32_t aoff = ((w * 16 + (l & 15)) * SXP + k0 + ((l >> 4) << 3)) * 2;
            uint32_t ah[4], al[4];
            ldsm4(ah, uXh + aoff);
            ldsm4(al, uXl + aoff);
            #pragma unroll
            for (int ntp = 0; ntp < 3; ntp++) {
                uint32_t boff = ((ntp * 16 + ((l >> 4) << 3) + (l & 7)) * SXP + k0 + (l & 8)) * 2;
                uint32_t bh[4], bl[4];
                ldsm4(bh, uQh + boff);
                ldsm4(bl, uQl + boff);
                mma_bf16(acc[ntp * 2],     ah, bh[0], bh[1]);
                mma_bf16(acc[ntp * 2],     ah, bl[0], bl[1]);
                mma_bf16(acc[ntp * 2],     al, bh[0], bh[1]);
                mma_bf16(acc[ntp * 2 + 1], ah, bh[2], bh[3]);
                mma_bf16(acc[ntp * 2 + 1], ah, bl[2], bl[3]);
                mma_bf16(acc[ntp * 2 + 1], al, bh[2], bh[3]);
            }
        }
    };

    // preamble: chunk0 -> A, chunk1 -> B (both in flight); stage chunk0
    LDGXA(0);
    LDGQ(0);
    LDGXB(32);
    STSA(0);
    __syncthreads();
    // pairs (1,2),(3,4),...,(21,22)
    for (int ch = 1; ch < 23; ch += 2) {
        LDGXA((ch + 1) * 32);     // chunk ch+1 -> A (distance 2)
        LDGQ(ch * 32);
        COMP((ch - 1) & 1);
        STSB(ch & 1);             // chunk ch from B (loaded a full pair ago)
        __syncthreads();
        LDGXB((ch + 2) * 32);     // chunk ch+2 -> B
        LDGQ((ch + 1) * 32);
        COMP(ch & 1);
        STSA((ch + 1) & 1);       // chunk ch+1 from A
        __syncthreads();
    }
    // leftover: chunk23 is in B (loaded at ch=21 second half)
    LDGQ(23 * 32);
    COMP(0);                      // chunk22
    STSB(1);                      // chunk23
    __syncthreads();
    COMP(1);                      // chunk23
    __syncthreads();

    float* stage = reinterpret_cast<float*>(dsm);
    {
        int yl = w * 16 + (l >> 2);
        #pragma unroll
        for (int nt = 0; nt < 6; nt++) {
            int r = nt * 8 + (l & 3) * 2;
            stage[r * 136 + yl]           = acc[nt][0];
            stage[(r + 1) * 136 + yl]     = acc[nt][1];
            stage[r * 136 + yl + 8]       = acc[nt][2];
            stage[(r + 1) * 136 + yl + 8] = acc[nt][3];
        }
    }
    __syncthreads();
    float* ob = g_sc + (size_t)b * RR * SS;
    #pragma unroll
    for (int i = tid; i < 48 * 32; i += 256) {
        int r = i >> 5, c4 = i & 31;
        float4 v = *reinterpret_cast<float4*>(&stage[r * 136 + c4 * 4]);
        *reinterpret_cast<float4*>(ob + (size_t)r * SS + y0 + c4 * 4) = v;
    }
}

// =================== Kernel 3: softmax -> bf16 hi/lo ===================
__global__ void __launch_bounds__(256) k_softmax() {
    const int row = blockIdx.x;
    const float* p = g_sc + (size_t)row * SS;
    __nv_bfloat16* oh = g_ath + (size_t)row * SS;
    __nv_bfloat16* ol = g_atl + (size_t)row * SS;
    __shared__ float sv[SS];
    __shared__ float red[8];

    float mx = -1e30f;
    for (int t = threadIdx.x; t < SS / 4; t += 256) {
        float4 v = reinterpret_cast<const float4*>(p)[t];
        reinterpret_cast<float4*>(sv)[t] = v;
        mx = fmaxf(mx, fmaxf(fmaxf(v.x, v.y), fmaxf(v.z, v.w)));
    }
    #pragma unroll
    for (int o = 16; o; o >>= 1) mx = fmaxf(mx, __shfl_xor_sync(0xffffffffu, mx, o));
    if ((threadIdx.x & 31) == 0) red[threadIdx.x >> 5] = mx;
    __syncthreads();
    float m = red[0];
    #pragma unroll
    for (int k = 1; k < 8; k++) m = fmaxf(m, red[k]);
    __syncthreads();

    float sum = 0.f;
    for (int t = threadIdx.x; t < SS / 4; t += 256) {
        float4 v = reinterpret_cast<float4*>(sv)[t];
        v.x = expf(v.x - m); v.y = expf(v.y - m);
        v.z = expf(v.z - m); v.w = expf(v.w - m);
        reinterpret_cast<float4*>(sv)[t] = v;
        sum += v.x + v.y + v.z + v.w;
    }
    #pragma unroll
    for (int o = 16; o; o >>= 1) sum += __shfl_xor_sync(0xffffffffu, sum, o);
    if ((threadIdx.x & 31) == 0) red[threadIdx.x >> 5] = sum;
    __syncthreads();
    float tot = 0.f;
    #pragma unroll
    for (int k = 0; k < 8; k++) tot += red[k];
    float inv = 1.0f / tot;

    for (int t = threadIdx.x; t < SS / 4; t += 256) {
        float4 v = reinterpret_cast<float4*>(sv)[t];
        v.x *= inv; v.y *= inv; v.z *= inv; v.w *= inv;
        reinterpret_cast<uint2*>(oh)[t] = make_uint2(pk2(v.x, v.y), pk2(v.z, v.w));
        reinterpret_cast<uint2*>(ol)[t] = make_uint2(pk2(rz(v.x), rz(v.y)), pk2(rz(v.z), rz(v.w)));
    }
}

// =========== Kernel 4 (ncu slot): ctx (exact R11 form — control) ===========
#define CXP 72
#define CX_TOT 64512
__global__ void __launch_bounds__(192) k_ctx_mma(const float* __restrict__ x) {
    extern __shared__ __align__(16) char dsm[];
    const uint32_t ub = smem_u32(dsm);

    const int tid = threadIdx.x, w = tid >> 5, l = tid & 31;
    const int ct = blockIdx.x;
    const int sp = blockIdx.y;
    const int b  = blockIdx.z;
    const int c0 = ct * 64;
    const int ybase = sp * (SS / NSPLIT);   // 512 y per split

    const float* xb = x + (size_t)b * SS * HH + c0;
    const __nv_bfloat16* ah = g_ath + (size_t)b * RR * SS;
    const __nv_bfloat16* al = g_atl + (size_t)b * RR * SS;

    const int mt = w >> 1;
    const int cbase = (w & 1) * 32;

    float acc[4][4];
    #pragma unroll
    for (int n = 0; n < 4; n++)
        #pragma unroll
        for (int k = 0; k < 4; k++) acc[n][k] = 0.f;

    float4 px[6];
    uint4 pah[2], pal[2];

    auto LDG = [&](int yc) {
        #pragma unroll
        for (int it = 0; it < 6; it++) {
            int t = tid + 192 * it;
            if (t < 1024) {
                int row = t >> 4, c4 = t & 15;
                px[it] = *reinterpret_cast<const float4*>(
                    xb + (size_t)(yc + row) * HH + c4 * 4);
            }
        }
        #pragma unroll
        for (int it = 0; it < 2; it++) {
            int t = tid + 192 * it;
            if (t < 384) {
                int row = t >> 3, q = t & 7;
                pah[it] = *reinterpret_cast<const uint4*>(ah + (size_t)row * SS + yc + q * 8);
                pal[it] = *reinterpret_cast<const uint4*>(al + (size_t)row * SS + yc + q * 8);
            }
        }
    };
    auto STS = [&](int buf) {
        char* ahb = dsm + buf * 6912;
        char* alb = dsm + 13824 + buf * 6912;
        char* xhb = dsm + 27648 + buf * 9216;
        char* xlb = dsm + 46080 + buf * 9216;
        #pragma unroll
        for (int it = 0; it < 6; it++) {
            int t = tid + 192 * it;
            if (t < 1024) {
                int row = t >> 4, c4 = t & 15;
                float4 v = px[it];
                *reinterpret_cast<uint2*>(xhb + (row * CXP + c4 * 4) * 2) =
                    make_uint2(pk2(v.x, v.y), pk2(v.z, v.w));
                *reinterpret_cast<uint2*>(xlb + (row * CXP + c4 * 4) * 2) =
                    make_uint2(pk2(rz(v.x), rz(v.y)), pk2(rz(v.z), rz(v.w)));
            }
        }
        #pragma unroll
        for (int it = 0; it < 2; it++) {
            int t = tid + 192 * it;
            if (t < 384) {
                int row = t >> 3, q = t & 7;
                *reinterpret_cast<uint4*>(ahb + (row * CXP + q * 8) * 2) = pah[it];
                *reinterpret_cast<uint4*>(alb + (row * CXP + q * 8) * 2) = pal[it];
            }
        }
    };
    auto COMP = [&](int buf) {
        uint32_t uAh = ub + buf * 6912;
        uint32_t uAl = ub + 13824 + buf * 6912;
        uint32_t uXh = ub + 27648 + buf * 9216;
        uint32_t uXl = ub + 46080 + buf * 9216;
        #pragma unroll
        for (int ks = 0; ks < 4; ks++) {
            const int k0 = ks * 16;
            uint32_t aoff = ((mt * 16 + (l & 15)) * CXP + k0 + ((l >> 4) << 3)) * 2;
            uint32_t fa_h[4], fa_l[4];
            ldsm4(fa_h, uAh + aoff);
            ldsm4(fa_l, uAl + aoff);
            #pragma unroll
            for (int ntp = 0; ntp < 2; ntp++) {
                uint32_t boff = ((k0 + (l & 15)) * CXP + cbase + ntp * 16 + ((l >> 4) << 3)) * 2;
                uint32_t fb_h[4], fb_l[4];
                ldsm4t(fb_h, uXh + boff);
                ldsm4t(fb_l, uXl + boff);
                mma_bf16(acc[ntp * 2],     fa_h, fb_h[0], fb_h[1]);
                mma_bf16(acc[ntp * 2],     fa_h, fb_l[0], fb_l[1]);
                mma_bf16(acc[ntp * 2],     fa_l, fb_h[0], fb_h[1]);
                mma_bf16(acc[ntp * 2 + 1], fa_h, fb_h[2], fb_h[3]);
                mma_bf16(acc[ntp * 2 + 1], fa_h, fb_l[2], fb_l[3]);
                mma_bf16(acc[ntp * 2 + 1], fa_l, fb_h[2], fb_h[3]);
            }
        }
    };

    const int NCH = (SS / NSPLIT) / 64;   // 8 chunks
    LDG(ybase);
    STS(0);
    __syncthreads();
    for (int ch = 1; ch < NCH; ch++) {
        LDG(ybase + ch * 64);
        COMP((ch - 1) & 1);
        STS(ch & 1);
        __syncthreads();
    }
    COMP((NCH - 1) & 1);

    float* ob = g_part + (size_t)((b * NSPLIT + sp) * RR) * HH + c0;
    int r0 = mt * 16 + (l >> 2);
    #pragma unroll
    for (int nt = 0; nt < 4; nt++) {
        int c = cbase + nt * 8 + (l & 3) * 2;
        *reinterpret_cast<float2*>(ob + (size_t)r0 * HH + c)       = make_float2(acc[nt][0], acc[nt][1]);
        *reinterpret_cast<float2*>(ob + (size_t)(r0 + 8) * HH + c) = make_float2(acc[nt][2], acc[nt][3]);
    }
}

// =================== Kernel 5: reduce split-K ===================
__global__ void __launch_bounds__(256) k_reduce() {
    int o = blockIdx.x * 256 + threadIdx.x;
    int b = o / (RR * HH);
    int rc = o - b * (RR * HH);
    const float* p = g_part + (size_t)b * NSPLIT * RR * HH + rc;
    float a = 0.f;
    #pragma unroll
    for (int s = 0; s < NSPLIT; s++) a += p[(size_t)s * RR * HH];
    g_ctx[o] = a;
}

// ========== Kernel 6: o[b,t,e] = ctx[b, (e>>6)*4+t, :] · wkv[HH+e, :] ==========
__global__ void __launch_bounds__(256) k_out1(const float* __restrict__ wkv) {
    int bt = blockIdx.x;
    int b = bt >> 2, t = bt & 3;
    int e0 = blockIdx.y * 128;
    __shared__ float sc_[2][HH];
    for (int idx = threadIdx.x; idx < 2 * HH / 4; idx += 256) {
        int hh = idx / (HH / 4), c4 = idx % (HH / 4);
        int h = (e0 >> 6) + hh;
        reinterpret_cast<float4*>(&sc_[hh][0])[c4] =
            reinterpret_cast<const float4*>(g_ctx + (size_t)(b * RR + h * NBN + t) * HH)[c4];
    }
    __syncthreads();
    int e = e0 + (threadIdx.x >> 1);
    int half = threadIdx.x & 1;
    const float4* wr = reinterpret_cast<const float4*>(wkv + (size_t)(HH + e) * HH) + half * 96;
    const float4* cr = reinterpret_cast<const float4*>(&sc_[(e - e0) >> 6][0]) + half * 96;
    float a = 0.f;
    #pragma unroll 4
    for (int c4 = 0; c4 < 96; c4++) {
        float4 wv = wr[c4], cv = cr[c4];
        a += wv.x * cv.x + wv.y * cv.y + wv.z * cv.z + wv.w * cv.w;
    }
    a += __shfl_xor_sync(0xffffffffu, a, 1);
    if (half == 0) g_o[(size_t)bt * HH + e] = a;
}

// ========== Kernel 7: out[b,t,j] = g_o[b,t,:] · wout[j,:] + bout[j] ==========
__global__ void __launch_bounds__(256) k_out2(const float* __restrict__ wout,
                                              const float* __restrict__ bout,
                                              float* __restrict__ out) {
    int bt = blockIdx.x;
    int j0 = blockIdx.y * 128;
    __shared__ float so[HH];
    for (int idx = threadIdx.x; idx < HH / 4; idx += 256)
        reinterpret_cast<float4*>(so)[idx] =
            reinterpret_cast<const float4*>(g_o + (size_t)bt * HH)[idx];
    __syncthreads();
    int j = j0 + (threadIdx.x >> 1);
    int half = threadIdx.x & 1;
    const float4* wr = reinterpret_cast<const float4*>(wout + (size_t)j * HH) + half * 96;
    const float4* sr = reinterpret_cast<const float4*>(so) + half * 96;
    float a = 0.f;
    #pragma unroll 4
    for (int c4 = 0; c4 < 96; c4++) {
        float4 wv = wr[c4], sv = sr[c4];
        a += wv.x * sv.x + wv.y * sv.y + wv.z * sv.z + wv.w * sv.w;
    }
    a += __shfl_xor_sync(0xffffffffu, a, 1);
    if (half == 0) out[(size_t)bt * HH + j] = a + bout[j];
}

// ---------------------------------------------------------------------------
extern "C" void kernel_launch(void* const* d_in, const int* in_sizes, int n_in,
                              void* d_out, int out_size) {
    const float* x    = (const float*)d_in[0];
    const float* wkv  = (const float*)d_in[1];
    const float* wq   = (const float*)d_in[2];
    const float* wout = (const float*)d_in[3];
    const float* bout = (const float*)d_in[4];
    float* out = (float*)d_out;

    cudaFuncSetAttribute(k_scores_mma, cudaFuncAttributeMaxDynamicSharedMemorySize, SC_TOT);
    cudaFuncSetAttribute(k_ctx_mma,    cudaFuncAttributeMaxDynamicSharedMemorySize, CX_TOT);

    k_qw<<<dim3(3, BB * NH), 256>>>(x, wq, wkv);                 // 1
    k_scores_mma<<<dim3(SS / 128, BB), 256, SC_TOT>>>(x);        // 2
    k_softmax<<<BB * RR, 256>>>();                               // 3
    k_ctx_mma<<<dim3(HH / 64, NSPLIT, BB), 192, CX_TOT>>>(x);    // 4 (ncu slot, control)
    k_reduce<<<(BB * RR * HH) / 256, 256>>>();                   // 5
    k_out1<<<dim3(BB * NBN, HH / 128), 256>>>(wkv);              // 6
    k_out2<<<dim3(BB * NBN, HH / 128), 256>>>(wout, bout, out);  // 7
}